// round 10
// baseline (speedup 1.0000x reference)
#include <cuda_runtime.h>

// StateSpaceDiffusionModel: y[b,h,:] = causal_conv(u[b,h,:], f[h,:])
// reduced exactly to a scalar order-64 IIR+FIR (transposed direct form II),
// then FOLDED into an exact 2-step state map with no y in the recurrence:
//   S_i(t+2) = S_{i+2}(t) + G_i*S1 + D_i*S2 + P_i*u0 + Q_i*u1
//   y0 = c0*u0 + S1 ;  y1 = c0*u1 + chat1*u0 + A'1*S1 + S2
// where (A'_i = a_{i-1} for i<=64 else 0; C'_i = c_i for i<=63 else 0;
//        chat_i = C'_i + A'_i*c0):
//   G_i = A'_{i+1} + A'_i*A'_1 ; D_i = A'_i
//   P_i = chat_{i+1} + A'_i*chat_1 ; Q_i = chat_i
// All multiplicands (S1,S2,u0,u1) are iteration-start values -> the carried
// chain has no y computation, no pack, no shuffle.

#define HH 512
#define NN 64
#define BB 16
#define LL 2048

__device__ float g_c[HH * NN];                 // c taps (scan uses c0 only)
__device__ float g_G[HH * NN];                 // folded taps, slot i=1..64 at [i-1]
__device__ float g_D[HH * NN];
__device__ float g_P[HH * NN];
__device__ float g_Q[HH * NN];

// ---------------- Kernel 1: per-head coefficients + folding ----------------
__global__ void coef_kernel(const float* __restrict__ k) {
    __shared__ float sha[NN];   // a taps (A'(i) = sha[i-1])
    __shared__ float shc[NN];   // c taps (C'(i) = shc[i], i<=63)
    __shared__ float shd[NN];
    __shared__ float shP[NN];
    __shared__ float shsum;
    int h = blockIdx.x;
    int j = threadIdx.x;
    float kv = k[h * NN + j];
    float kc = fminf(fmaxf(kv, 1.0f / 16.0f), 1.0f);
    sha[j] = kc;  // reuse as scratch for the sum
    __syncthreads();
    if (j == 0) {
        float s = 0.f;
        for (int i = 0; i < NN; i++) s += sha[i];
        shsum = s;
    }
    __syncthreads();
    float kn = kc / shsum;                       // L1-normalized clamped k
    float s = (j < NN - 1) ? (1.0f + kn) : kn;   // column L1 norm of (A + b k^T)
    float w = kn / s;                            // M[0, j]
    shd[j] = 1.0f / s;                           // subdiagonal
    __syncthreads();
    if (j == 0) {
        float P = 1.f;
        for (int i = 0; i < NN; i++) { shP[i] = P; P *= shd[i]; }
    }
    __syncthreads();
    float Pj = shP[j];
    float aj = w * Pj;     // IIR taps a_j
    float cj = kv * Pj;    // FIR taps c_j (original k!)
    __syncthreads();       // sha scratch no longer needed
    sha[j] = aj;
    shc[j] = cj;
    g_c[h * NN + j] = cj;
    __syncthreads();

    // ---- folded 2-step coefficients for slot i = j+1 (1..64) ----
    float c0 = shc[0];
    float A1 = sha[0];
    float chat1 = shc[1] + A1 * c0;              // chat_1
    float Ai   = sha[j];                          // A'(i)
    float Aip1 = (j + 1 < NN) ? sha[j + 1] : 0.f; // A'(i+1)
    float Ci   = (j + 1 <= 63) ? shc[j + 1] : 0.f;     // C'(i),  i = j+1
    float Cip1 = (j + 2 <= 63) ? shc[j + 2] : 0.f;     // C'(i+1)
    float chat_i   = Ci   + Ai   * c0;
    float chat_ip1 = Cip1 + Aip1 * c0;
    g_G[h * NN + j] = Aip1 + Ai * A1;
    g_D[h * NN + j] = Ai;
    g_P[h * NN + j] = chat_ip1 + Ai * chat1;
    g_Q[h * NN + j] = chat_i;
}

// ---------------- packed f32x2 helpers ----------------
typedef unsigned long long ull;
__device__ __forceinline__ ull pack2(float lo, float hi) {
    ull r; asm("mov.b64 %0, {%1,%2};" : "=l"(r) : "f"(lo), "f"(hi)); return r;
}
__device__ __forceinline__ void unpack2(ull v, float& lo, float& hi) {
    asm("mov.b64 {%0,%1}, %2;" : "=f"(lo), "=f"(hi) : "l"(v));
}
__device__ __forceinline__ ull fma2(ull a, ull b, ull c) {
    ull d; asm("fma.rn.f32x2 %0, %1, %2, %3;" : "=l"(d) : "l"(a), "l"(b), "l"(c)); return d;
}
__device__ __forceinline__ ull mul2(ull a, ull b) {
    ull d; asm("mul.rn.f32x2 %0, %1, %2;" : "=l"(d) : "l"(a), "l"(b)); return d;
}
__device__ __forceinline__ ull add2(ull a, ull b) {
    ull d; asm("add.rn.f32x2 %0, %1, %2;" : "=l"(d) : "l"(a), "l"(b)); return d;
}

// ---------------- Kernel 2: folded scan, 8 lanes/seq -----------------------
// Warp = 4 sequences x 8 lanes. Redundant head: ALL lanes carry scalars
// S1, S2. Tail: lane r owns pairs p=0..3, base slot s = 8r+3+2p, i.e.
// T[p] = (S_s, S_{s+1}), covering slots 3..66 (65,66 are zeros).
// Per 2-step iteration (all state read at iteration start):
//   bc34 = lane0's old T[0] = (S3,S4)      [shfl, off-chain]
//   tb   = next lane's old T[0]            [shfl_down, off-chain; r==7 -> 0]
//   y0 = c0*u0 + S1 ; y1 = A'1*S1 + chat1*u0 + c0*u1 + S2     [side outputs]
//   S1'' = G1*S1 + D1*S2 + (P1*u0 + Q1*u1 + S3)     (2-stage head loop)
//   S2'' = G2*S1 + D2*S2 + (P2*u0 + Q2*u1 + S4)
//   T''[p] = add2( fma2(Pt,u0d, fma2(Qt,u1d, T[p+1]|tb)),     (3-stage tail)
//                  fma2(Gt,S1d, mul2(Dt,S2d)) )
#define PD 2   // float4 FIFO slots; each slot feeds 2 iterations (4 timesteps)

__global__ void __launch_bounds__(128, 4)
scan_kernel(const float* __restrict__ u, float* __restrict__ y) {
    int warp = blockIdx.x * (blockDim.x >> 5) + (threadIdx.x >> 5);
    int lane = threadIdx.x & 31;
    int g = lane >> 3;   // sequence within warp (0..3)
    int r = lane & 7;    // lane within group (0..7)
    int leader = lane & ~7;
    int seq = warp * 4 + g;           // 0..8191
    int h = seq & (HH - 1);
    const float4* ubase4 = (const float4*)(u + (size_t)seq * LL);
    ull* ybase2 = (ull*)(y + (size_t)seq * LL);

    int h64 = h * NN;

    // ---- tail taps: pair p, base slot s = 8r+3+2p; tap(m)=arr[m-1] if m<=64 ----
    ull Gt[4], Dt[4], Pt[4], Qt[4], T[4];
#pragma unroll
    for (int p = 0; p < 4; p++) {
        int s = 8 * r + 3 + 2 * p;
        float G0 = (s     <= 64) ? g_G[h64 + s - 1] : 0.f;
        float G1v= (s + 1 <= 64) ? g_G[h64 + s]     : 0.f;
        float D0 = (s     <= 64) ? g_D[h64 + s - 1] : 0.f;
        float D1v= (s + 1 <= 64) ? g_D[h64 + s]     : 0.f;
        float P0 = (s     <= 64) ? g_P[h64 + s - 1] : 0.f;
        float P1v= (s + 1 <= 64) ? g_P[h64 + s]     : 0.f;
        float Q0 = (s     <= 64) ? g_Q[h64 + s - 1] : 0.f;
        float Q1v= (s + 1 <= 64) ? g_Q[h64 + s]     : 0.f;
        Gt[p] = pack2(G0, G1v);
        Dt[p] = pack2(D0, D1v);
        Pt[p] = pack2(P0, P1v);
        Qt[p] = pack2(Q0, Q1v);
        T[p] = 0ull;
    }

    // ---- head taps (slots 1,2) + output taps ----
    float hG1 = g_G[h64 + 0], hD1 = g_D[h64 + 0], hP1 = g_P[h64 + 0], hQ1 = g_Q[h64 + 0];
    float hG2 = g_G[h64 + 1], hD2 = g_D[h64 + 1], hP2 = g_P[h64 + 1], hQ2 = g_Q[h64 + 1];
    float c0h = g_c[h64 + 0];
    float A1h = hD1;    // A'(1)
    float hc1 = hQ1;    // chat_1
    float S1 = 0.f, S2 = 0.f;

    // prologue: fill FIFO (each slot = 4 timesteps = 2 iterations)
    float4 buf[PD];
#pragma unroll
    for (int j = 0; j < PD; j++) buf[j] = ubase4[j];

    const int NQ = LL / 4;  // 512 float4 chunks
    for (int q0 = 0; q0 < NQ; q0 += PD) {
#pragma unroll
        for (int j = 0; j < PD; j++) {
            int q = q0 + j;
            float4 cur = buf[j];
            int qp = q + PD; if (qp > NQ - 1) qp = NQ - 1;
            buf[j] = ubase4[qp];   // refill (clamped; unused if OOB)

#pragma unroll
            for (int half = 0; half < 2; half++) {
                float u0 = half ? cur.z : cur.x;
                float u1 = half ? cur.w : cur.y;

                // off-chain shuffles of iteration-start tail state
                ull bc34 = __shfl_sync(0xffffffffu, T[0], leader);  // (S3,S4)
                ull tb   = __shfl_down_sync(0xffffffffu, T[0], 1);  // next lane pair0
                if (r == 7) tb = 0ull;

                // side outputs (identical in all lanes; nothing depends on y)
                float y0 = fmaf(c0h, u0, S1);
                float y1 = fmaf(A1h, S1, fmaf(hc1, u0, fmaf(c0h, u1, S2)));

                // dup-packed multiplicands
                ull S1d = pack2(S1, S1), S2d = pack2(S2, S2);
                ull u0d = pack2(u0, u0), u1d = pack2(u1, u1);

                // head update (2-stage carried loop)
                float S3o, S4o; unpack2(bc34, S3o, S4o);
                float hb1 = fmaf(hP1, u0, fmaf(hQ1, u1, S3o));
                float hb2 = fmaf(hP2, u0, fmaf(hQ2, u1, S4o));
                float S1n = fmaf(hG1, S1, fmaf(hD1, S2, hb1));
                float S2n = fmaf(hG2, S1, fmaf(hD2, S2, hb2));

                // tail update: tree form, 3-stage carried loop
                ull n0 = add2(fma2(Pt[0], u0d, fma2(Qt[0], u1d, T[1])),
                              fma2(Gt[0], S1d, mul2(Dt[0], S2d)));
                ull n1 = add2(fma2(Pt[1], u0d, fma2(Qt[1], u1d, T[2])),
                              fma2(Gt[1], S1d, mul2(Dt[1], S2d)));
                ull n2 = add2(fma2(Pt[2], u0d, fma2(Qt[2], u1d, T[3])),
                              fma2(Gt[2], S1d, mul2(Dt[2], S2d)));
                ull n3 = add2(fma2(Pt[3], u0d, fma2(Qt[3], u1d, tb)),
                              fma2(Gt[3], S1d, mul2(Dt[3], S2d)));
                T[0] = n0; T[1] = n1; T[2] = n2; T[3] = n3;
                S1 = S1n; S2 = S2n;

                if (r == 0)
                    ybase2[2 * q + half] = pack2(y0, y1);
            }
        }
    }
}

extern "C" void kernel_launch(void* const* d_in, const int* in_sizes, int n_in,
                              void* d_out, int out_size) {
    const float* u = (const float*)d_in[0];
    const float* k = (const float*)d_in[1];
    if (n_in >= 2 && in_sizes[0] == HH * NN) {  // defensive: swap if order differs
        u = (const float*)d_in[1];
        k = (const float*)d_in[0];
    }
    float* y = (float*)d_out;

    coef_kernel<<<HH, NN>>>(k);
    // 8192 sequences, 4 per warp, 4 warps per 128-thread CTA -> 512 CTAs
    scan_kernel<<<(BB * HH) / 16, 128>>>(u, y);
}

// round 11
// speedup vs baseline: 1.0528x; 1.0528x over previous
#include <cuda_runtime.h>

// StateSpaceDiffusionModel: y[b,h,:] = causal_conv(u[b,h,:], f[h,:])
// reduced exactly to a scalar order-64 IIR+FIR, then FOLDED into an exact
// 2-step state map with no y in the recurrence (validated in R9):
//   S_i(t+2) = S_{i+2}(t) + G_i*S1 + D_i*S2 + P_i*u0 + Q_i*u1   (i=1..64)
//   y0 = c0*u0 + S1 ;  y1 = A'1*S1 + chat1*u0 + c0*u1 + S2
// with A'_i = a_{i-1} (i<=64), C'_i = c_i (i<=63), chat_i = C'_i + A'_i*c0,
//   G_i = A'_{i+1} + A'_i*A'_1 ; D_i = A'_i
//   P_i = chat_{i+1} + A'_i*chat_1 ; Q_i = chat_i
//
// R10: dense 16-fma2 tail (coefficient-packed, no dup-data MOVs), tiny
// redundant scalar head (slots 1,2), and SOFTWARE-PIPELINED boundary
// shuffles (issued on fresh T[0] at iter end, consumed next iter via
// late-join bases) so SHFL latency is off every carried chain.

#define HH 512
#define NN 64
#define BB 16
#define LL 2048

__device__ float g_c[HH * NN];   // c taps (scan uses c0 only)
__device__ float g_G[HH * NN];   // folded taps, slot i=1..64 stored at [i-1]
__device__ float g_D[HH * NN];
__device__ float g_P[HH * NN];
__device__ float g_Q[HH * NN];

// ---------------- Kernel 1: per-head coefficients + folding ----------------
__global__ void coef_kernel(const float* __restrict__ k) {
    __shared__ float sha[NN];   // a taps (A'(i) = sha[i-1])
    __shared__ float shc[NN];   // c taps (C'(i) = shc[i], i<=63)
    __shared__ float shd[NN];
    __shared__ float shP[NN];
    __shared__ float shsum;
    int h = blockIdx.x;
    int j = threadIdx.x;
    float kv = k[h * NN + j];
    float kc = fminf(fmaxf(kv, 1.0f / 16.0f), 1.0f);
    sha[j] = kc;  // scratch for the sum
    __syncthreads();
    if (j == 0) {
        float s = 0.f;
        for (int i = 0; i < NN; i++) s += sha[i];
        shsum = s;
    }
    __syncthreads();
    float kn = kc / shsum;                       // L1-normalized clamped k
    float s = (j < NN - 1) ? (1.0f + kn) : kn;   // column L1 norm of (A + b k^T)
    float w = kn / s;                            // M[0, j]
    shd[j] = 1.0f / s;                           // subdiagonal
    __syncthreads();
    if (j == 0) {
        float P = 1.f;
        for (int i = 0; i < NN; i++) { shP[i] = P; P *= shd[i]; }
    }
    __syncthreads();
    float Pj = shP[j];
    float aj = w * Pj;     // IIR taps a_j
    float cj = kv * Pj;    // FIR taps c_j (original k!)
    __syncthreads();       // scratch no longer needed
    sha[j] = aj;
    shc[j] = cj;
    g_c[h * NN + j] = cj;
    __syncthreads();

    // folded 2-step coefficients for slot i = j+1 (1..64)
    float c0 = shc[0];
    float A1 = sha[0];
    float chat1 = shc[1] + A1 * c0;
    float Ai   = sha[j];                               // A'(i)
    float Aip1 = (j + 1 < NN) ? sha[j + 1] : 0.f;      // A'(i+1)
    float Ci   = (j + 1 <= 63) ? shc[j + 1] : 0.f;     // C'(i)
    float Cip1 = (j + 2 <= 63) ? shc[j + 2] : 0.f;     // C'(i+1)
    float chat_i   = Ci   + Ai   * c0;
    float chat_ip1 = Cip1 + Aip1 * c0;
    g_G[h * NN + j] = Aip1 + Ai * A1;
    g_D[h * NN + j] = Ai;
    g_P[h * NN + j] = chat_ip1 + Ai * chat1;
    g_Q[h * NN + j] = chat_i;
}

// ---------------- packed f32x2 helpers ----------------
typedef unsigned long long ull;
__device__ __forceinline__ ull pack2(float lo, float hi) {
    ull r; asm("mov.b64 %0, {%1,%2};" : "=l"(r) : "f"(lo), "f"(hi)); return r;
}
__device__ __forceinline__ ull fma2(ull a, ull b, ull c) {
    ull d; asm("fma.rn.f32x2 %0, %1, %2, %3;" : "=l"(d) : "l"(a), "l"(b), "l"(c)); return d;
}
__device__ __forceinline__ ull mul2(ull a, ull b) {
    ull d; asm("mul.rn.f32x2 %0, %1, %2;" : "=l"(d) : "l"(a), "l"(b)); return d;
}
__device__ __forceinline__ ull add2(ull a, ull b) {
    ull d; asm("add.rn.f32x2 %0, %1, %2;" : "=l"(d) : "l"(a), "l"(b)); return d;
}

// ---------------- Kernel 2: folded scan, pipelined shuffles ----------------
// Warp = 4 sequences x 8 lanes. Head: ALL lanes carry scalars S1,S2.
// Tail: lane r owns pairs T[p] = slots (3+8r+2p, 4+8r+2p), p=0..3
// (slots 3..66; 65,66 have zero taps and zero base -> stay 0).
// Per 2-step iteration (all multiplicands are iteration-start values):
//   T''[p] = fma2((G_s,D_{s+1}),S12, fma2((D_s,G_{s+1}),S21,
//            fma2((P_s,Q_{s+1}),U01, fma2((Q_s,P_{s+1}),U10, base))))
//   base: T_old[p+1] for p<3; for p==3 a late-join add2 of `tb`
//   S1'' = G1*S1+D1*S2+P1*u0+Q1*u1 (+S3old late)   [scalar, redundant]
//   S2'' = G2*S1+D2*S2+P2*u0+Q2*u1 (+S4old late)
//   y0 = c0*u0 + S1 ; y1 = A'1*S1 + chat1*u0 + c0*u1 + S2   [side outputs]
// End of iter: shfl fresh T[0] -> bc34 (head base) and tb (tail base),
// consumed NEXT iteration => SHFL latency fully hidden.
#define PD 4   // float4 FIFO slots; each slot feeds 2 iterations (4 timesteps)

__global__ void __launch_bounds__(128, 4)
scan_kernel(const float* __restrict__ u, float* __restrict__ y) {
    int warp = blockIdx.x * (blockDim.x >> 5) + (threadIdx.x >> 5);
    int lane = threadIdx.x & 31;
    int g = lane >> 3;   // sequence within warp (0..3)
    int r = lane & 7;    // lane within group (0..7)
    int leader = lane & ~7;
    int seq = warp * 4 + g;           // 0..8191
    int h = seq & (HH - 1);
    const float4* ubase4 = (const float4*)(u + (size_t)seq * LL);
    ull* ybase2 = (ull*)(y + (size_t)seq * LL);

    int h64 = h * NN;

    // ---- tail taps: pair p, base slot s = 3+8r+2p; tap(m)=arr[m-1] if m<=64 ----
    // coefficient-packed for data pairs: cS12=(G_s,D_{s+1}) cS21=(D_s,G_{s+1})
    //                                    cU01=(P_s,Q_{s+1}) cU10=(Q_s,P_{s+1})
    ull cS12[4], cS21[4], cU01[4], cU10[4], T[4];
#pragma unroll
    for (int p = 0; p < 4; p++) {
        int s = 3 + 8 * r + 2 * p;
        float Gs  = (s     <= 64) ? g_G[h64 + s - 1] : 0.f;
        float Gs1 = (s + 1 <= 64) ? g_G[h64 + s]     : 0.f;
        float Ds  = (s     <= 64) ? g_D[h64 + s - 1] : 0.f;
        float Ds1 = (s + 1 <= 64) ? g_D[h64 + s]     : 0.f;
        float Ps  = (s     <= 64) ? g_P[h64 + s - 1] : 0.f;
        float Ps1 = (s + 1 <= 64) ? g_P[h64 + s]     : 0.f;
        float Qs  = (s     <= 64) ? g_Q[h64 + s - 1] : 0.f;
        float Qs1 = (s + 1 <= 64) ? g_Q[h64 + s]     : 0.f;
        cS12[p] = pack2(Gs, Ds1);
        cS21[p] = pack2(Ds, Gs1);
        cU01[p] = pack2(Ps, Qs1);
        cU10[p] = pack2(Qs, Ps1);
        T[p] = 0ull;
    }

    // ---- head taps (slots 1,2) + output taps ----
    float hG1 = g_G[h64 + 0], hD1 = g_D[h64 + 0], hP1 = g_P[h64 + 0], hQ1 = g_Q[h64 + 0];
    float hG2 = g_G[h64 + 1], hD2 = g_D[h64 + 1], hP2 = g_P[h64 + 1], hQ2 = g_Q[h64 + 1];
    float c0h = g_c[h64 + 0];
    float A1h = hD1;    // A'(1)
    float hc1 = hQ1;    // chat_1
    float S1 = 0.f, S2 = 0.f;

    // pipelined boundary values (state starts at zero)
    float S3o = 0.f, S4o = 0.f;   // (S3,S4) at start of next iter, from lane 0
    ull tb = 0ull;                 // next lane's T[0] at start of next iter

    // prologue: fill FIFO (each slot = 4 timesteps = 2 iterations)
    float4 buf[PD];
#pragma unroll
    for (int j = 0; j < PD; j++) buf[j] = ubase4[j];

    const int NQ = LL / 4;  // 512 float4 chunks
    for (int q0 = 0; q0 < NQ; q0 += PD) {
#pragma unroll
        for (int j = 0; j < PD; j++) {
            int q = q0 + j;
            float4 cur = buf[j];
            int qp = q + PD; if (qp > NQ - 1) qp = NQ - 1;
            buf[j] = ubase4[qp];   // refill (clamped; unused if OOB)

#pragma unroll
            for (int half = 0; half < 2; half++) {
                float u0 = half ? cur.z : cur.x;
                float u1 = half ? cur.w : cur.y;

                // data pairs (natural + swapped)
                ull S12 = pack2(S1, S2), S21 = pack2(S2, S1);
                ull U01 = pack2(u0, u1), U10 = pack2(u1, u0);

                // side outputs (identical in all lanes; nothing depends on y)
                float y0 = fmaf(c0h, u0, S1);
                float y1 = fmaf(A1h, S1, fmaf(hc1, u0, fmaf(c0h, u1, S2)));

                // head update, late-join bases (S3o/S4o arrived last iter)
                float h1 = fmaf(hG1, S1, fmaf(hD1, S2, fmaf(hP1, u0, hQ1 * u1)));
                float h2 = fmaf(hG2, S1, fmaf(hD2, S2, fmaf(hP2, u0, hQ2 * u1)));
                float S1n = h1 + S3o;
                float S2n = h2 + S4o;

                // tail update: p=0..2 chained on local bases, p=3 late-join tb
                ull n0 = fma2(cS12[0], S12, fma2(cS21[0], S21,
                          fma2(cU01[0], U01, fma2(cU10[0], U10, T[1]))));
                ull n1 = fma2(cS12[1], S12, fma2(cS21[1], S21,
                          fma2(cU01[1], U01, fma2(cU10[1], U10, T[2]))));
                ull n2 = fma2(cS12[2], S12, fma2(cS21[2], S21,
                          fma2(cU01[2], U01, fma2(cU10[2], U10, T[3]))));
                ull a3 = fma2(cS12[3], S12, fma2(cS21[3], S21,
                          fma2(cU01[3], U01, mul2(cU10[3], U10))));
                ull n3 = add2(a3, tb);
                T[0] = n0; T[1] = n1; T[2] = n2; T[3] = n3;
                S1 = S1n; S2 = S2n;

                // pipelined shuffles of FRESH T[0]: consumed next iteration
                {
                    ull bc34 = __shfl_sync(0xffffffffu, T[0], leader);
                    ull tbn  = __shfl_down_sync(0xffffffffu, T[0], 1);
                    if (r == 7) tbn = 0ull;
                    tb = tbn;
                    asm("mov.b64 {%0,%1}, %2;" : "=f"(S3o), "=f"(S4o) : "l"(bc34));
                }

                if (r == 0)
                    ybase2[2 * q + half] = pack2(y0, y1);
            }
        }
    }
}

extern "C" void kernel_launch(void* const* d_in, const int* in_sizes, int n_in,
                              void* d_out, int out_size) {
    const float* u = (const float*)d_in[0];
    const float* k = (const float*)d_in[1];
    if (n_in >= 2 && in_sizes[0] == HH * NN) {  // defensive: swap if order differs
        u = (const float*)d_in[1];
        k = (const float*)d_in[0];
    }
    float* y = (float*)d_out;

    coef_kernel<<<HH, NN>>>(k);
    // 8192 sequences, 4 per warp, 4 warps per 128-thread CTA -> 512 CTAs
    scan_kernel<<<(BB * HH) / 16, 128>>>(u, y);
}

// round 12
// speedup vs baseline: 1.2272x; 1.1656x over previous
#include <cuda_runtime.h>

// StateSpaceDiffusionModel: y[b,h,:] = causal_conv(u[b,h,:], f[h,:])
// reduced exactly to a scalar order-64 IIR+FIR (transposed direct form II):
//   y_t = c0*u_t + S[1]
//   S[i] <- S[i+1] + A'[i]*y_t + C'[i]*u_t   (merged delay line, i=1..64)
// A'[i] = a_{i-1} (1<=i<=64), C'[i] = c_i (1<=i<=63).
//
// R11 = R3 body (best measured) with BALANCED LAUNCH: 32-thread CTAs,
// grid 2048 -> 13/14 warps per SM (vs 12/16 with 128-thread CTAs).
// Per-warp code unchanged (no block-level sync anywhere).

#define HH 512
#define NN 64
#define BB 16
#define LL 2048

__device__ float g_a[HH * NN];
__device__ float g_c[HH * NN];

// ---------------- Kernel 1: per-head coefficients (trivial) ----------------
__global__ void coef_kernel(const float* __restrict__ k) {
    __shared__ float sh[NN];
    __shared__ float shd[NN];
    __shared__ float shP[NN];
    __shared__ float shsum;
    int h = blockIdx.x;
    int j = threadIdx.x;
    float kv = k[h * NN + j];
    float kc = fminf(fmaxf(kv, 1.0f / 16.0f), 1.0f);
    sh[j] = kc;
    __syncthreads();
    if (j == 0) {
        float s = 0.f;
        for (int i = 0; i < NN; i++) s += sh[i];
        shsum = s;
    }
    __syncthreads();
    float kn = kc / shsum;                       // L1-normalized clamped k
    float s = (j < NN - 1) ? (1.0f + kn) : kn;   // column L1 norm of (A + b k^T)
    float w = kn / s;                            // M[0, j]
    shd[j] = 1.0f / s;                           // M[j+1, j] subdiagonal
    __syncthreads();
    if (j == 0) {
        float P = 1.f;
        for (int i = 0; i < NN; i++) { shP[i] = P; P *= shd[i]; }
    }
    __syncthreads();
    float Pj = shP[j];
    g_a[h * NN + j] = w * Pj;    // IIR taps
    g_c[h * NN + j] = kv * Pj;   // FIR taps (original k!)
}

// ---------------- packed f32x2 helpers ----------------
typedef unsigned long long ull;
__device__ __forceinline__ ull pack2(float lo, float hi) {
    ull r; asm("mov.b64 %0, {%1,%2};" : "=l"(r) : "f"(lo), "f"(hi)); return r;
}
__device__ __forceinline__ void unpack2(ull v, float& lo, float& hi) {
    asm("mov.b64 {%0,%1}, %2;" : "=f"(lo), "=f"(hi) : "l"(v));
}
__device__ __forceinline__ ull fma2(ull a, ull b, ull c) {
    ull d; asm("fma.rn.f32x2 %0, %1, %2, %3;" : "=l"(d) : "l"(a), "l"(b), "l"(c)); return d;
}

// ---------------- Kernel 2: fused scan, 8 lanes per sequence ----------------
// Two timesteps per iteration. pair p = slots (2p+1, 2p+2), p = 0..31.
//   S''_p = S_{p+1} + Ae_p*y0 + Ao_p*y1 + Ce_p*u0 + Co_p*u1
// Warp = 4 sequences x 8 lanes; lane r owns pairs 4r..4r+3 (slots 8r+1..8r+8).
// u read as float4 (2 iterations per load) through a 4-slot register FIFO;
// y written as float4 every 2 iterations.
#define PD2 4   // float4 FIFO slots; each slot feeds 2 iterations (4 timesteps)

__global__ void __launch_bounds__(32)
scan_kernel(const float* __restrict__ u, float* __restrict__ y) {
    int warp = blockIdx.x;            // one warp per CTA
    int lane = threadIdx.x & 31;
    int g = lane >> 3;   // sequence within warp (0..3)
    int r = lane & 7;    // lane within group (0..7)
    int leader = lane & ~7;
    int seq = warp * 4 + g;           // 0..8191
    int h = seq & (HH - 1);
    const float4* ubase4 = (const float4*)(u + (size_t)seq * LL);
    float4* ybase4 = (float4*)(y + (size_t)seq * LL);

    const float* ah = g_a + h * NN;
    const float* ch = g_c + h * NN;

    ull Ae[4], Ao[4], Ce[4], Co[4], S[4];
#pragma unroll
    for (int i = 0; i < 4; i++) {
        int p = r * 4 + i;
        int i1 = 2 * p + 1, i2 = 2 * p + 2, i3 = 2 * p + 3;
        // A'[idx] = a[idx-1] for 1<=idx<=64 ; C'[idx] = c[idx] for 1<=idx<=63
        float A1 = (i1 <= 64) ? ah[i1 - 1] : 0.f;
        float A2 = (i2 <= 64) ? ah[i2 - 1] : 0.f;
        float A3 = (i3 <= 64) ? ah[i3 - 1] : 0.f;
        float C1 = (i1 <= 63) ? ch[i1] : 0.f;
        float C2 = (i2 <= 63) ? ch[i2] : 0.f;
        float C3 = (i3 <= 63) ? ch[i3] : 0.f;
        Ae[i] = pack2(A2, A3);
        Ao[i] = pack2(A1, A2);
        Ce[i] = pack2(C2, C3);
        Co[i] = pack2(C1, C2);
        S[i] = 0ull;
    }
    float c0h = ch[0], c1h = ch[1], a0h = ah[0];
    float SS1 = 0.f, SS2 = 0.f;   // unpacked old S[0] (valid on r==0)

    // prologue: fill FIFO (each slot covers 4 timesteps)
    float4 buf[PD2];
#pragma unroll
    for (int j = 0; j < PD2; j++)
        buf[j] = ubase4[j];

    const int NQ = LL / 4;  // 512 four-step chunks
    for (int q0 = 0; q0 < NQ; q0 += PD2) {
#pragma unroll
        for (int j = 0; j < PD2; j++) {
            int q = q0 + j;             // chunk index: timesteps 4q..4q+3
            float4 cur = buf[j];
            int qp = q + PD2;
            if (qp > NQ - 1) qp = NQ - 1;   // clamped refill (unused if OOB)
            buf[j] = ubase4[qp];

            float2 yout01, yout23;
            // ---- iteration A: timesteps 4q, 4q+1 (u = cur.x, cur.y) ----
            {
                ull sn = __shfl_down_sync(0xffffffffu, S[0], 1);
                if (r == 7) sn = 0ull;
                float u0 = cur.x, u1 = cur.y;
                float y0 = fmaf(c0h, u0, SS1);
                float y1 = fmaf(a0h, y0, fmaf(c1h, u0, fmaf(c0h, u1, SS2)));
                ull ypk = __shfl_sync(0xffffffffu, pack2(y0, y1), leader);
                float y0b, y1b; unpack2(ypk, y0b, y1b);
                ull y0pk = pack2(y0b, y0b), y1pk = pack2(y1b, y1b);
                ull u0pk = pack2(u0, u0), u1pk = pack2(u1, u1);
#pragma unroll
                for (int i = 0; i < 3; i++)
                    S[i] = fma2(Ae[i], y0pk, fma2(Ao[i], y1pk,
                            fma2(Ce[i], u0pk, fma2(Co[i], u1pk, S[i + 1]))));
                S[3] = fma2(Ae[3], y0pk, fma2(Ao[3], y1pk,
                         fma2(Ce[3], u0pk, fma2(Co[3], u1pk, sn))));
                unpack2(S[0], SS1, SS2);
                yout01 = make_float2(y0, y1);
            }
            // ---- iteration B: timesteps 4q+2, 4q+3 (u = cur.z, cur.w) ----
            {
                ull sn = __shfl_down_sync(0xffffffffu, S[0], 1);
                if (r == 7) sn = 0ull;
                float u0 = cur.z, u1 = cur.w;
                float y0 = fmaf(c0h, u0, SS1);
                float y1 = fmaf(a0h, y0, fmaf(c1h, u0, fmaf(c0h, u1, SS2)));
                ull ypk = __shfl_sync(0xffffffffu, pack2(y0, y1), leader);
                float y0b, y1b; unpack2(ypk, y0b, y1b);
                ull y0pk = pack2(y0b, y0b), y1pk = pack2(y1b, y1b);
                ull u0pk = pack2(u0, u0), u1pk = pack2(u1, u1);
#pragma unroll
                for (int i = 0; i < 3; i++)
                    S[i] = fma2(Ae[i], y0pk, fma2(Ao[i], y1pk,
                            fma2(Ce[i], u0pk, fma2(Co[i], u1pk, S[i + 1]))));
                S[3] = fma2(Ae[3], y0pk, fma2(Ao[3], y1pk,
                         fma2(Ce[3], u0pk, fma2(Co[3], u1pk, sn))));
                unpack2(S[0], SS1, SS2);
                yout23 = make_float2(y0, y1);
            }

            if (r == 0)
                ybase4[q] = make_float4(yout01.x, yout01.y, yout23.x, yout23.y);
        }
    }
}

extern "C" void kernel_launch(void* const* d_in, const int* in_sizes, int n_in,
                              void* d_out, int out_size) {
    const float* u = (const float*)d_in[0];
    const float* k = (const float*)d_in[1];
    if (n_in >= 2 && in_sizes[0] == HH * NN) {  // defensive: swap if order differs
        u = (const float*)d_in[1];
        k = (const float*)d_in[0];
    }
    float* y = (float*)d_out;

    coef_kernel<<<HH, NN>>>(k);
    // 8192 sequences, 4 per warp, ONE warp per CTA -> 2048 CTAs.
    // 2048 warps over 148 SMs = 13 or 14 per SM (1.2% imbalance vs 15.6%
    // with 128-thread CTAs).
    scan_kernel<<<(BB * HH) / 4, 32>>>(u, y);
}